// round 12
// baseline (speedup 1.0000x reference)
#include <cuda_runtime.h>
#include <cuda_fp16.h>

#define NP 8192
#define THREADS 256
#define IPT 2
#define IROWS (THREADS * IPT)       // 512 i's per ib
#define IB (NP / IROWS)             // 16 i-blocks
#define JC 37
#define JCHUNK 222                  // even; last chunk 200 (even)
#define JPMAX (JCHUNK / 2)

static_assert(IB * IROWS == NP, "i coverage");
static_assert(JC * JCHUNK >= NP, "j coverage");
static_assert(IB * JC == 592, "perfect wave: 148 SMs x 4 blocks");

// Scratch [jc][i]: coalesced both sides; every slot written once per launch.
__device__ float2 g_part[JC * NP];
// Per-ib arrival counters; atomicInc wraps back to 0 each launch (graph-safe).
__device__ unsigned g_sync[IB];

__device__ __forceinline__ float sqa(float x) {
    float r; asm("sqrt.approx.f32 %0, %1;" : "=f"(r) : "f"(x)); return r;
}
__device__ __forceinline__ unsigned h2u(__half2 h) {
    return *reinterpret_cast<const unsigned*>(&h);
}

#define T35   0.70020753f   // tan(35 deg)
#define INVT  1.4281480f    // 1/tan(35 deg)
#define TT    0.49029058f   // tan^2(35 deg)

struct h2pair { __half2 x, y; };

__global__ __launch_bounds__(THREADS, 4)
void pair_kernel(const float2* __restrict__ past, const float2* __restrict__ pos,
                 const int* __restrict__ idxmask, const float* __restrict__ radii,
                 float* __restrict__ out) {
    __shared__ h2pair sj[JPMAX];
    __shared__ int isLast;
    const int ib = blockIdx.x;
    const int jc = blockIdx.y;
    const int tid = threadIdx.x;
    const int jbase = jc * JCHUNK;
    const int jend = min(NP - jbase, JCHUNK);   // 222 or 200
    const int jp = jend >> 1;

    const float4* __restrict__ posj4 = (const float4*)(pos + jbase);
    for (int t = tid; t < jp; t += THREADS) {
        const float4 v = posj4[t];
        sj[t].x = __floats2half2_rn(v.x, v.z);
        sj[t].y = __floats2half2_rn(v.y, v.w);
    }
    __syncthreads();

    const int i0 = ib * IROWS;
    const __half2 TT2 = __float2half2_rn(TT);

    __half2 hc[IPT], hs[IPT], ha[IPT], hct[IPT], hnst[IPT], hbt[IPT];
    float sum0[IPT], sum1[IPT];
    int cnt0[IPT], cnt1[IPT];

    #pragma unroll
    for (int k = 0; k < IPT; k++) {
        const int i = i0 + k * THREADS + tid;
        const float2 p = pos[i];
        const float2 q = past[i];
        const float dx = p.x - q.x;
        const float dy = p.y - q.y;
        const float l2 = fmaf(dx, dx, dy * dy);
        float rin; asm("rsqrt.approx.f32 %0, %1;" : "=f"(rin) : "f"(l2));
        const float ci = (l2 > 0.0f) ? dx * rin : 1.0f;
        const float si = (l2 > 0.0f) ? dy * rin : 0.0f;
        const float av = -fmaf(p.x, ci, p.y * si);      // -(x c + y s)
        const float bv =  fmaf(p.x, si, -(p.y * ci));   //  x s - y c
        hc[k]   = __float2half2_rn(ci);
        hs[k]   = __float2half2_rn(si);
        ha[k]   = __float2half2_rn(av);
        hct[k]  = __float2half2_rn(ci * INVT);          // y-row / tan35:
        hnst[k] = __float2half2_rn(-si * INVT);         //   arc test |yb| < xp
        hbt[k]  = __float2half2_rn(bv * INVT);
        sum0[k] = 0.0f; sum1[k] = 0.0f;
        cnt0[k] = 0; cnt1[k] = 0;
    }

    #pragma unroll 8
    for (int m = 0; m < jp; m++) {
        const __half2 px = sj[m].x;
        const __half2 py = sj[m].y;
        #pragma unroll
        for (int k = 0; k < IPT; k++) {
            const __half2 xp = __hfma2(px, hc[k],  __hfma2(py, hs[k],   ha[k]));
            const __half2 yb = __hfma2(py, hct[k], __hfma2(px, hnst[k], hbt[k]));
            const __half2 sq = __hfma2(xp, xp, __hmul2(__hmul2(yb, yb), TT2));
            const unsigned ayb = h2u(yb) & 0x7FFF7FFFu;   // fp16x2 |.| via LOP3 (alu)
            // Arc test first; cvt+sqrt+adds fully predicated -> only ~19% of
            // pairs exercise the MUFU port and the long-latency chain.
            asm volatile(
                "{\n\t"
                ".reg .pred p, q;\n\t"
                ".reg .b16 h0, h1;\n\t"
                ".reg .f32 f0, f1;\n\t"
                "setp.lt.f16x2 p|q, %4, %5;\n\t"
                "mov.b32 {h0, h1}, %6;\n\t"
                "@p cvt.f32.f16 f0, h0;\n\t"
                "@q cvt.f32.f16 f1, h1;\n\t"
                "@p sqrt.approx.f32 f0, f0;\n\t"
                "@q sqrt.approx.f32 f1, f1;\n\t"
                "@p add.f32 %0, %0, f0;\n\t"
                "@q add.f32 %1, %1, f1;\n\t"
                "@p add.s32 %2, %2, 1;\n\t"
                "@q add.s32 %3, %3, 1;\n\t"
                "}"
                : "+f"(sum0[k]), "+f"(sum1[k]), "+r"(cnt0[k]), "+r"(cnt1[k])
                : "r"(ayb), "r"(h2u(xp)), "r"(h2u(sq)));
        }
    }

    #pragma unroll
    for (int k = 0; k < IPT; k++) {
        const int i = i0 + k * THREADS + tid;
        float s0 = sum0[k], s1 = sum1[k];
        int c0 = cnt0[k], c1 = cnt1[k];
        if (i >= jbase && i < jbase + jend) {
            // Remove self-pair via identical lanewise recompute (cvt+sqrt here
            // match the predicated loop path bit-for-bit on the same input).
            const int loc = i - jbase;
            const int m = loc >> 1, lane = loc & 1;
            const __half2 px = sj[m].x, py = sj[m].y;
            const __half2 xp = __hfma2(px, hc[k],  __hfma2(py, hs[k],   ha[k]));
            const __half2 yb = __hfma2(py, hct[k], __hfma2(px, hnst[k], hbt[k]));
            const __half2 sq = __hfma2(xp, xp, __hmul2(__hmul2(yb, yb), TT2));
            const float dl = sqa(__low2float(sq));
            const float dh = sqa(__high2float(sq));
            const unsigned ayb = h2u(yb) & 0x7FFF7FFFu;
            const unsigned xpb = h2u(xp);
            int rl = 0, rh = 0;
            asm volatile(
                "{\n\t"
                ".reg .pred p, q;\n\t"
                "setp.lt.f16x2 p|q, %2, %3;\n\t"
                "selp.b32 %0, 1, 0, p;\n\t"
                "selp.b32 %1, 1, 0, q;\n\t"
                "}"
                : "=r"(rl), "=r"(rh) : "r"(ayb), "r"(xpb));
            if (lane) { if (rh) { s1 -= dh; c1--; } }
            else      { if (rl) { s0 -= dl; c0--; } }
        }
        g_part[jc * NP + i] = make_float2(s0 + s1, (float)(c0 + c1));   // coalesced
    }

    // ── fused finalize: last jc-block for this ib reduces all partials ──
    __threadfence();                       // publish g_part writes
    __syncthreads();                       // all warps done writing
    if (tid == 0)
        isLast = (atomicInc(&g_sync[ib], JC - 1) == JC - 1);  // wraps to 0 per launch
    __syncthreads();
    if (isLast) {
        // Each thread reduces 2 adjacent rows via LDG.128 (coalesced, high MLP).
        const int i = i0 + tid * 2;
        float sA = 0.0f, cA = 0.0f, sB = 0.0f, cB = 0.0f;
        #pragma unroll
        for (int q = 0; q < JC; q++) {
            const float4 v = *(const float4*)&g_part[q * NP + i];  // {sA,cA,sB,cB}
            sA += v.x; cA += v.y;
            sB += v.z; cB += v.w;
        }
        float meanA = (cA > 0.0f) ? sA / cA : 0.0f;
        float meanB = (cB > 0.0f) ? sB / cB : 0.0f;
        meanA = fminf(fmaxf(meanA, 0.2f), 5.0f);
        meanB = fminf(fmaxf(meanB, 0.2f), 5.0f);
        const float rA = fmaf((meanA - 0.2f) * (1.0f / 4.8f), 3.5f, 0.5f);
        const float rB = fmaf((meanB - 0.2f) * (1.0f / 4.8f), 3.5f, 0.5f);
        out[i]     = idxmask[i]     ? rA : radii[i];
        out[i + 1] = idxmask[i + 1] ? rB : radii[i + 1];
    }
}

extern "C" void kernel_launch(void* const* d_in, const int* in_sizes, int n_in,
                              void* d_out, int out_size) {
    const float2* past = (const float2*)d_in[0];
    const float2* pos  = (const float2*)d_in[1];
    const int* idxm    = (const int*)d_in[2];   // bool widened to int32
    const float* radii = (const float*)d_in[3];
    float* out = (float*)d_out;

    dim3 grid(IB, JC);
    pair_kernel<<<grid, THREADS>>>(past, pos, idxm, radii, out);
}

// round 13
// speedup vs baseline: 1.3368x; 1.3368x over previous
#include <cuda_runtime.h>
#include <cuda_fp16.h>

#define NP 8192
#define THREADS 256
#define IPT 2
#define IROWS (THREADS * IPT)       // 512 i's per ib
#define IB (NP / IROWS)             // 16 i-blocks
#define JC 46
#define JCHUNK 180                  // even; 46*180 = 8280 >= 8192; last chunk 92 (even)
#define JPMAX (JCHUNK / 2)

static_assert(IB * IROWS == NP, "i coverage");
static_assert(JC * JCHUNK >= NP, "j coverage");
static_assert(IB * JC == 736, "~5 blocks per SM (148 SMs)");

// Scratch [jc][i]: coalesced both sides; every slot written once per launch.
__device__ float2 g_part[JC * NP];
// Per-ib arrival counters; atomicInc wraps back to 0 each launch (graph-safe).
__device__ unsigned g_sync[IB];

__device__ __forceinline__ float sqa(float x) {
    float r; asm("sqrt.approx.f32 %0, %1;" : "=f"(r) : "f"(x)); return r;
}
__device__ __forceinline__ unsigned h2u(__half2 h) {
    return *reinterpret_cast<const unsigned*>(&h);
}

#define T35   0.70020753f   // tan(35 deg)
#define INVT  1.4281480f    // 1/tan(35 deg)
#define TT    0.49029058f   // tan^2(35 deg)

struct h2pair { __half2 x, y; };

__global__ __launch_bounds__(THREADS, 5)
void pair_kernel(const float2* __restrict__ past, const float2* __restrict__ pos,
                 const int* __restrict__ idxmask, const float* __restrict__ radii,
                 float* __restrict__ out) {
    __shared__ h2pair sj[JPMAX];
    __shared__ int isLast;
    const int ib = blockIdx.x;
    const int jc = blockIdx.y;
    const int tid = threadIdx.x;
    const int jbase = jc * JCHUNK;
    const int jend = min(NP - jbase, JCHUNK);   // 180 or 92, always even
    const int jp = jend >> 1;

    const float4* __restrict__ posj4 = (const float4*)(pos + jbase);
    for (int t = tid; t < jp; t += THREADS) {
        const float4 v = posj4[t];
        sj[t].x = __floats2half2_rn(v.x, v.z);
        sj[t].y = __floats2half2_rn(v.y, v.w);
    }
    __syncthreads();

    const int i0 = ib * IROWS;
    const __half2 TT2 = __float2half2_rn(TT);

    __half2 hc[IPT], hs[IPT], ha[IPT], hct[IPT], hnst[IPT], hbt[IPT];
    float sum0[IPT], sum1[IPT];
    int cnt0[IPT], cnt1[IPT];

    #pragma unroll
    for (int k = 0; k < IPT; k++) {
        const int i = i0 + k * THREADS + tid;
        const float2 p = pos[i];
        const float2 q = past[i];
        const float dx = p.x - q.x;
        const float dy = p.y - q.y;
        const float l2 = fmaf(dx, dx, dy * dy);
        float rin; asm("rsqrt.approx.f32 %0, %1;" : "=f"(rin) : "f"(l2));
        const float ci = (l2 > 0.0f) ? dx * rin : 1.0f;
        const float si = (l2 > 0.0f) ? dy * rin : 0.0f;
        const float av = -fmaf(p.x, ci, p.y * si);      // -(x c + y s)
        const float bv =  fmaf(p.x, si, -(p.y * ci));   //  x s - y c
        hc[k]   = __float2half2_rn(ci);
        hs[k]   = __float2half2_rn(si);
        ha[k]   = __float2half2_rn(av);
        hct[k]  = __float2half2_rn(ci * INVT);          // y-row / tan35:
        hnst[k] = __float2half2_rn(-si * INVT);         //   arc test |yb| < xp
        hbt[k]  = __float2half2_rn(bv * INVT);
        sum0[k] = 0.0f; sum1[k] = 0.0f;
        cnt0[k] = 0; cnt1[k] = 0;
    }

    #pragma unroll 8
    for (int m = 0; m < jp; m++) {
        const __half2 px = sj[m].x;
        const __half2 py = sj[m].y;
        #pragma unroll
        for (int k = 0; k < IPT; k++) {
            const __half2 xp = __hfma2(px, hc[k],  __hfma2(py, hs[k],   ha[k]));
            const __half2 yb = __hfma2(py, hct[k], __hfma2(px, hnst[k], hbt[k]));
            const __half2 sq = __hfma2(xp, xp, __hmul2(__hmul2(yb, yb), TT2));
            const float dl = sqa(__low2float(sq));
            const float dh = sqa(__high2float(sq));
            const unsigned ayb = h2u(yb) & 0x7FFF7FFFu;   // fp16x2 |.| via LOP3 (alu)
            // dual-predicate arc test: p=(|yb|.lo<xp.lo), q=(.hi); xp>0 implied
            asm volatile(
                "{\n\t"
                ".reg .pred p, q;\n\t"
                "setp.lt.f16x2 p|q, %4, %5;\n\t"
                "@p add.f32 %0, %0, %6;\n\t"
                "@q add.f32 %1, %1, %7;\n\t"
                "@p add.s32 %2, %2, 1;\n\t"
                "@q add.s32 %3, %3, 1;\n\t"
                "}"
                : "+f"(sum0[k]), "+f"(sum1[k]), "+r"(cnt0[k]), "+r"(cnt1[k])
                : "r"(ayb), "r"(h2u(xp)), "f"(dl), "f"(dh));
        }
    }

    #pragma unroll
    for (int k = 0; k < IPT; k++) {
        const int i = i0 + k * THREADS + tid;
        float s0 = sum0[k], s1 = sum1[k];
        int c0 = cnt0[k], c1 = cnt1[k];
        if (i >= jbase && i < jbase + jend) {
            // Remove self-pair via identical lanewise recompute.
            const int loc = i - jbase;
            const int m = loc >> 1, lane = loc & 1;
            const __half2 px = sj[m].x, py = sj[m].y;
            const __half2 xp = __hfma2(px, hc[k],  __hfma2(py, hs[k],   ha[k]));
            const __half2 yb = __hfma2(py, hct[k], __hfma2(px, hnst[k], hbt[k]));
            const __half2 sq = __hfma2(xp, xp, __hmul2(__hmul2(yb, yb), TT2));
            const float dl = sqa(__low2float(sq));
            const float dh = sqa(__high2float(sq));
            const unsigned ayb = h2u(yb) & 0x7FFF7FFFu;
            const unsigned xpb = h2u(xp);
            int rl = 0, rh = 0;
            asm volatile(
                "{\n\t"
                ".reg .pred p, q;\n\t"
                "setp.lt.f16x2 p|q, %2, %3;\n\t"
                "selp.b32 %0, 1, 0, p;\n\t"
                "selp.b32 %1, 1, 0, q;\n\t"
                "}"
                : "=r"(rl), "=r"(rh) : "r"(ayb), "r"(xpb));
            if (lane) { if (rh) { s1 -= dh; c1--; } }
            else      { if (rl) { s0 -= dl; c0--; } }
        }
        g_part[jc * NP + i] = make_float2(s0 + s1, (float)(c0 + c1));   // coalesced
    }

    // ── fused finalize: last jc-block for this ib reduces all partials ──
    __threadfence();                       // publish g_part writes
    __syncthreads();                       // all warps done writing
    if (tid == 0)
        isLast = (atomicInc(&g_sync[ib], JC - 1) == JC - 1);  // wraps to 0 per launch
    __syncthreads();
    if (isLast) {
        // Each thread reduces 2 adjacent rows via LDG.128 (coalesced, high MLP).
        const int i = i0 + tid * 2;
        float sA = 0.0f, cA = 0.0f, sB = 0.0f, cB = 0.0f;
        #pragma unroll
        for (int q = 0; q < JC; q++) {
            const float4 v = *(const float4*)&g_part[q * NP + i];  // {sA,cA,sB,cB}
            sA += v.x; cA += v.y;
            sB += v.z; cB += v.w;
        }
        float meanA = (cA > 0.0f) ? sA / cA : 0.0f;
        float meanB = (cB > 0.0f) ? sB / cB : 0.0f;
        meanA = fminf(fmaxf(meanA, 0.2f), 5.0f);
        meanB = fminf(fmaxf(meanB, 0.2f), 5.0f);
        const float rA = fmaf((meanA - 0.2f) * (1.0f / 4.8f), 3.5f, 0.5f);
        const float rB = fmaf((meanB - 0.2f) * (1.0f / 4.8f), 3.5f, 0.5f);
        out[i]     = idxmask[i]     ? rA : radii[i];
        out[i + 1] = idxmask[i + 1] ? rB : radii[i + 1];
    }
}

extern "C" void kernel_launch(void* const* d_in, const int* in_sizes, int n_in,
                              void* d_out, int out_size) {
    const float2* past = (const float2*)d_in[0];
    const float2* pos  = (const float2*)d_in[1];
    const int* idxm    = (const int*)d_in[2];   // bool widened to int32
    const float* radii = (const float*)d_in[3];
    float* out = (float*)d_out;

    dim3 grid(IB, JC);
    pair_kernel<<<grid, THREADS>>>(past, pos, idxm, radii, out);
}

// round 15
// speedup vs baseline: 1.8396x; 1.3762x over previous
#include <cuda_runtime.h>
#include <cuda_fp16.h>

#define NP 8192
#define THREADS 256
#define IPT 2
#define IROWS (THREADS * IPT)       // 512 i's per ib
#define IB (NP / IROWS)             // 16 i-blocks
#define JC 37
#define JCHUNK 224                  // jp=112 (14*8); last chunk 128 -> jp=64 (8*8)
#define JPMAX (JCHUNK / 2)

static_assert(IB * IROWS == NP, "i coverage");
static_assert(JC * JCHUNK >= NP, "j coverage");
static_assert(IB * JC == 592, "perfect wave: 148 SMs x 4 blocks");
static_assert((JPMAX % 8) == 0 && (((NP - (JC - 1) * JCHUNK) / 2) % 8) == 0, "8-blocks");

// Scratch [jc][i]: coalesced both sides; every slot written once per launch.
__device__ float2 g_part[JC * NP];
// Per-ib arrival counters; atomicInc wraps back to 0 each launch (graph-safe).
__device__ unsigned g_sync[IB];

__device__ __forceinline__ unsigned h2u(__half2 h) {
    return *reinterpret_cast<const unsigned*>(&h);
}
__device__ __forceinline__ __half2 u2h(unsigned u) {
    return *reinterpret_cast<const __half2*>(&u);
}

#define T35   0.70020753f   // tan(35 deg)
// d = sqrt(x'^2+y'^2) ~= A*x' + B*|y'| for |y'|/x' in [0, tan35], zero-mean LS fit
#define AFIT  0.96785f
#define BFIT  0.30996f

struct h2pair { __half2 x, y; };

__global__ __launch_bounds__(THREADS, 4)
void pair_kernel(const float2* __restrict__ past, const float2* __restrict__ pos,
                 const int* __restrict__ idxmask, const float* __restrict__ radii,
                 float* __restrict__ out) {
    __shared__ h2pair sj[JPMAX];
    __shared__ int isLast;
    const int ib = blockIdx.x;
    const int jc = blockIdx.y;
    const int tid = threadIdx.x;
    const int jbase = jc * JCHUNK;
    const int jend = min(NP - jbase, JCHUNK);   // 224 or 128
    const int jp = jend >> 1;                   // 112 or 64, multiple of 8

    const float4* __restrict__ posj4 = (const float4*)(pos + jbase);
    for (int t = tid; t < jp; t += THREADS) {
        const float4 v = posj4[t];
        sj[t].x = __floats2half2_rn(v.x, v.z);
        sj[t].y = __floats2half2_rn(v.y, v.w);
    }
    __syncthreads();

    const int i0 = ib * IROWS;
    const __half2 T2h = __float2half2_rn(T35);
    const __half2 A2  = __float2half2_rn(AFIT);
    const __half2 B2  = __float2half2_rn(BFIT);
    const __half2 Z2  = __float2half2_rn(0.0f);

    __half2 hc[IPT], hs[IPT], hns[IPT], ha[IPT], hb[IPT], cnth[IPT];
    float sumf[IPT];

    #pragma unroll
    for (int k = 0; k < IPT; k++) {
        const int i = i0 + k * THREADS + tid;
        const float2 p = pos[i];
        const float2 q = past[i];
        const float dx = p.x - q.x;
        const float dy = p.y - q.y;
        const float l2 = fmaf(dx, dx, dy * dy);
        float rin; asm("rsqrt.approx.f32 %0, %1;" : "=f"(rin) : "f"(l2));
        const float ci = (l2 > 0.0f) ? dx * rin : 1.0f;
        const float si = (l2 > 0.0f) ? dy * rin : 0.0f;
        const float av = -fmaf(p.x, ci, p.y * si);      // -(x c + y s)
        const float bv =  fmaf(p.x, si, -(p.y * ci));   //  x s - y c
        hc[k]  = __float2half2_rn(ci);
        hs[k]  = __float2half2_rn(si);
        hns[k] = __float2half2_rn(-si);
        ha[k]  = __float2half2_rn(av);
        hb[k]  = __float2half2_rn(bv);
        sumf[k] = 0.0f;
        cnth[k] = Z2;
    }

    for (int base = 0; base < jp; base += 8) {
        __half2 bs[IPT];
        #pragma unroll
        for (int k = 0; k < IPT; k++) bs[k] = Z2;
        #pragma unroll
        for (int mm = 0; mm < 8; mm++) {
            const int m = base + mm;
            const __half2 px = sj[m].x;
            const __half2 py = sj[m].y;
            #pragma unroll
            for (int k = 0; k < IPT; k++) {
                // true rotated coords: x' = xc+ys+a ; y' = yc-xs+b
                const __half2 xp = __hfma2(px, hc[k],  __hfma2(py, hs[k],  ha[k]));
                const __half2 yp = __hfma2(py, hc[k],  __hfma2(px, hns[k], hb[k]));
                const __half2 ayp = u2h(h2u(yp) & 0x7FFF7FFFu);   // |y'| (LOP3, alu)
                const __half2 tt = __hmul2(T2h, xp);
                const __half2 mask = __hlt2(ayp, tt);             // in-arc {1,0}
                // sqrt-free distance: valid on the masked domain r in [0,0.7]
                const __half2 dd = __hfma2(ayp, B2, __hmul2(xp, A2));
                bs[k]   = __hfma2(dd, mask, bs[k]);               // gated block sum
                cnth[k] = __hadd2(cnth[k], mask);                 // exact (<=112)
            }
        }
        #pragma unroll
        for (int k = 0; k < IPT; k++)                 // spill fp16 block sum -> f32
            sumf[k] += __low2float(bs[k]) + __high2float(bs[k]);
    }

    #pragma unroll
    for (int k = 0; k < IPT; k++) {
        const int i = i0 + k * THREADS + tid;
        float s = sumf[k];
        float c = __low2float(cnth[k]) + __high2float(cnth[k]);
        if (i >= jbase && i < jbase + jend) {
            // Remove self-pair: mask recompute is exact (fixes the count);
            // its distance contribution (~0.05) is subtracted approximately.
            const int loc = i - jbase;
            const int m = loc >> 1, lane = loc & 1;
            const __half2 px = sj[m].x, py = sj[m].y;
            const __half2 xp = __hfma2(px, hc[k],  __hfma2(py, hs[k],  ha[k]));
            const __half2 yp = __hfma2(py, hc[k],  __hfma2(px, hns[k], hb[k]));
            const __half2 ayp = u2h(h2u(yp) & 0x7FFF7FFFu);
            const __half2 tt = __hmul2(T2h, xp);
            const __half2 mask = __hlt2(ayp, tt);
            const __half2 dd = __hfma2(ayp, B2, __hmul2(xp, A2));
            const __half2 g = __hmul2(dd, mask);
            if (lane) { s -= __high2float(g); c -= __high2float(mask); }
            else      { s -= __low2float(g);  c -= __low2float(mask);  }
        }
        g_part[jc * NP + i] = make_float2(s, c);   // coalesced
    }

    // ── fused finalize: last jc-block for this ib reduces all partials ──
    __threadfence();                       // publish g_part writes
    __syncthreads();                       // all warps done writing
    if (tid == 0)
        isLast = (atomicInc(&g_sync[ib], JC - 1) == JC - 1);  // wraps to 0 per launch
    __syncthreads();
    if (isLast) {
        // Each thread reduces 2 adjacent rows via LDG.128 (coalesced, high MLP).
        const int i = i0 + tid * 2;
        float sA = 0.0f, cA = 0.0f, sB = 0.0f, cB = 0.0f;
        #pragma unroll
        for (int q = 0; q < JC; q++) {
            const float4 v = *(const float4*)&g_part[q * NP + i];  // {sA,cA,sB,cB}
            sA += v.x; cA += v.y;
            sB += v.z; cB += v.w;
        }
        float meanA = (cA > 0.0f) ? sA / cA : 0.0f;
        float meanB = (cB > 0.0f) ? sB / cB : 0.0f;
        meanA = fminf(fmaxf(meanA, 0.2f), 5.0f);
        meanB = fminf(fmaxf(meanB, 0.2f), 5.0f);
        const float rA = fmaf((meanA - 0.2f) * (1.0f / 4.8f), 3.5f, 0.5f);
        const float rB = fmaf((meanB - 0.2f) * (1.0f / 4.8f), 3.5f, 0.5f);
        out[i]     = idxmask[i]     ? rA : radii[i];
        out[i + 1] = idxmask[i + 1] ? rB : radii[i + 1];
    }
}

extern "C" void kernel_launch(void* const* d_in, const int* in_sizes, int n_in,
                              void* d_out, int out_size) {
    const float2* past = (const float2*)d_in[0];
    const float2* pos  = (const float2*)d_in[1];
    const int* idxm    = (const int*)d_in[2];   // bool widened to int32
    const float* radii = (const float*)d_in[3];
    float* out = (float*)d_out;

    dim3 grid(IB, JC);
    pair_kernel<<<grid, THREADS>>>(past, pos, idxm, radii, out);
}

// round 16
// speedup vs baseline: 2.1429x; 1.1648x over previous
#include <cuda_runtime.h>
#include <cuda_fp16.h>

#define NP 8192
#define THREADS 256
#define IPT 2
#define IROWS (THREADS * IPT)       // 512 i's per ib
#define IB (NP / IROWS)             // 16 i-blocks
#define JC 37
#define JCHUNK 224                  // jp=112 (14*8); last chunk 128 -> jp=64 (8*8)
#define JPMAX (JCHUNK / 2)

static_assert(IB * IROWS == NP, "i coverage");
static_assert(JC * JCHUNK >= NP, "j coverage");
static_assert(IB * JC == 592, "perfect wave: 148 SMs x 4 blocks");
static_assert((JPMAX % 8) == 0 && (((NP - (JC - 1) * JCHUNK) / 2) % 8) == 0, "8-blocks");

// Scratch [jc][i]: coalesced both sides; every slot written once per launch.
__device__ float2 g_part[JC * NP];
// Per-ib arrival counters; atomicInc wraps back to 0 each launch (graph-safe).
__device__ unsigned g_sync[IB];

__device__ __forceinline__ unsigned h2u(__half2 h) {
    return *reinterpret_cast<const unsigned*>(&h);
}
__device__ __forceinline__ __half2 u2h(unsigned u) {
    return *reinterpret_cast<const __half2*>(&u);
}

#define T35   0.70020753f   // tan(35 deg)
#define INVT  1.4281480f    // 1/tan(35 deg)
// d = sqrt(x'^2+y'^2) ~= A*x' + B*|y'| on |y'|/x' in [0, tan35] (zero-mean LS fit)
#define AFIT  0.96785f
#define BTFIT (0.30996f * 0.70020753f)   // B*T: applied to |y'|/T

struct h2pair { __half2 x, y; };

__global__ __launch_bounds__(THREADS, 4)
void pair_kernel(const float2* __restrict__ past, const float2* __restrict__ pos,
                 const int* __restrict__ idxmask, const float* __restrict__ radii,
                 float* __restrict__ out) {
    __shared__ h2pair sj[JPMAX];
    __shared__ int isLast;
    const int ib = blockIdx.x;
    const int jc = blockIdx.y;
    const int tid = threadIdx.x;
    const int jbase = jc * JCHUNK;
    const int jend = min(NP - jbase, JCHUNK);   // 224 or 128
    const int jp = jend >> 1;                   // 112 or 64, multiple of 8

    const float4* __restrict__ posj4 = (const float4*)(pos + jbase);
    for (int t = tid; t < jp; t += THREADS) {
        const float4 v = posj4[t];
        sj[t].x = __floats2half2_rn(v.x, v.z);
        sj[t].y = __floats2half2_rn(v.y, v.w);
    }
    __syncthreads();

    const int i0 = ib * IROWS;
    const __half2 A2  = __float2half2_rn(AFIT);
    const __half2 BT2 = __float2half2_rn(BTFIT);
    const __half2 Z2  = __float2half2_rn(0.0f);

    __half2 hc[IPT], hs[IPT], ha[IPT], hct[IPT], hnst[IPT], hbt[IPT];
    float sumf[IPT];
    unsigned cntb[IPT];

    #pragma unroll
    for (int k = 0; k < IPT; k++) {
        const int i = i0 + k * THREADS + tid;
        const float2 p = pos[i];
        const float2 q = past[i];
        const float dx = p.x - q.x;
        const float dy = p.y - q.y;
        const float l2 = fmaf(dx, dx, dy * dy);
        float rin; asm("rsqrt.approx.f32 %0, %1;" : "=f"(rin) : "f"(l2));
        const float ci = (l2 > 0.0f) ? dx * rin : 1.0f;
        const float si = (l2 > 0.0f) ? dy * rin : 0.0f;
        const float av = -fmaf(p.x, ci, p.y * si);      // -(x c + y s)
        const float bv =  fmaf(p.x, si, -(p.y * ci));   //  x s - y c
        hc[k]   = __float2half2_rn(ci);
        hs[k]   = __float2half2_rn(si);
        ha[k]   = __float2half2_rn(av);
        hct[k]  = __float2half2_rn(ci * INVT);          // y-row / tan35:
        hnst[k] = __float2half2_rn(-si * INVT);         //   arc test |yb| < xp
        hbt[k]  = __float2half2_rn(bv * INVT);
        sumf[k] = 0.0f;
        cntb[k] = 0u;
    }

    for (int base = 0; base < jp; base += 8) {
        __half2 bs[IPT];
        #pragma unroll
        for (int k = 0; k < IPT; k++) bs[k] = Z2;
        #pragma unroll
        for (int mm = 0; mm < 8; mm++) {
            const int m = base + mm;
            const __half2 px = sj[m].x;
            const __half2 py = sj[m].y;
            #pragma unroll
            for (int k = 0; k < IPT; k++) {
                const __half2 xp = __hfma2(px, hc[k],  __hfma2(py, hs[k],   ha[k]));
                const __half2 yb = __hfma2(py, hct[k], __hfma2(px, hnst[k], hbt[k]));
                const __half2 ayb = u2h(h2u(yb) & 0x7FFF7FFFu);     // |yb| (alu)
                const unsigned mask = __hlt2_mask(ayb, xp);         // 0xFFFF/0 per half
                // sqrt-free distance: A*xp + (B*T)*|yb| = A*x' + B*|y'|
                const __half2 dd = __hfma2(ayb, BT2, __hmul2(xp, A2));
                const __half2 gated = u2h(mask & h2u(dd));          // exact select (alu)
                bs[k] = __hadd2(bs[k], gated);
                cntb[k] += (mask & 0x10001u);                       // per-lane int count (alu)
            }
        }
        #pragma unroll
        for (int k = 0; k < IPT; k++)                 // spill fp16 block sum -> f32
            sumf[k] += __low2float(bs[k]) + __high2float(bs[k]);
    }

    #pragma unroll
    for (int k = 0; k < IPT; k++) {
        const int i = i0 + k * THREADS + tid;
        float s = sumf[k];
        float c = (float)((cntb[k] & 0xFFFFu) + (cntb[k] >> 16));
        if (i >= jbase && i < jbase + jend) {
            // Remove self-pair via identical lanewise recompute.
            const int loc = i - jbase;
            const int m = loc >> 1, lane = loc & 1;
            const __half2 px = sj[m].x, py = sj[m].y;
            const __half2 xp = __hfma2(px, hc[k],  __hfma2(py, hs[k],   ha[k]));
            const __half2 yb = __hfma2(py, hct[k], __hfma2(px, hnst[k], hbt[k]));
            const __half2 ayb = u2h(h2u(yb) & 0x7FFF7FFFu);
            const unsigned mask = __hlt2_mask(ayb, xp);
            const __half2 dd = __hfma2(ayb, BT2, __hmul2(xp, A2));
            const __half2 gated = u2h(mask & h2u(dd));
            if (lane) { s -= __high2float(gated); c -= (float)((mask >> 16) & 1u); }
            else      { s -= __low2float(gated);  c -= (float)(mask & 1u); }
        }
        g_part[jc * NP + i] = make_float2(s, c);   // coalesced
    }

    // ── fused finalize: last jc-block for this ib reduces all partials ──
    __threadfence();                       // publish g_part writes
    __syncthreads();                       // all warps done writing
    if (tid == 0)
        isLast = (atomicInc(&g_sync[ib], JC - 1) == JC - 1);  // wraps to 0 per launch
    __syncthreads();
    if (isLast) {
        // Each thread reduces 2 adjacent rows via LDG.128 (coalesced, high MLP).
        const int i = i0 + tid * 2;
        float sA = 0.0f, cA = 0.0f, sB = 0.0f, cB = 0.0f;
        #pragma unroll
        for (int q = 0; q < JC; q++) {
            const float4 v = *(const float4*)&g_part[q * NP + i];  // {sA,cA,sB,cB}
            sA += v.x; cA += v.y;
            sB += v.z; cB += v.w;
        }
        float meanA = (cA > 0.0f) ? sA / cA : 0.0f;
        float meanB = (cB > 0.0f) ? sB / cB : 0.0f;
        meanA = fminf(fmaxf(meanA, 0.2f), 5.0f);
        meanB = fminf(fmaxf(meanB, 0.2f), 5.0f);
        const float rA = fmaf((meanA - 0.2f) * (1.0f / 4.8f), 3.5f, 0.5f);
        const float rB = fmaf((meanB - 0.2f) * (1.0f / 4.8f), 3.5f, 0.5f);
        out[i]     = idxmask[i]     ? rA : radii[i];
        out[i + 1] = idxmask[i + 1] ? rB : radii[i + 1];
    }
}

extern "C" void kernel_launch(void* const* d_in, const int* in_sizes, int n_in,
                              void* d_out, int out_size) {
    const float2* past = (const float2*)d_in[0];
    const float2* pos  = (const float2*)d_in[1];
    const int* idxm    = (const int*)d_in[2];   // bool widened to int32
    const float* radii = (const float*)d_in[3];
    float* out = (float*)d_out;

    dim3 grid(IB, JC);
    pair_kernel<<<grid, THREADS>>>(past, pos, idxm, radii, out);
}